// round 1
// baseline (speedup 1.0000x reference)
#include <cuda_runtime.h>
#include <math.h>

#define BSZ   2
#define NSEQ  2048
#define CDIM  768
#define HH    12
#define DHD   64
#define MROWS (BSZ * NSEQ)   // 4096

// Scratch (device globals — allocation-free contract)
__device__ float g_Q[MROWS * CDIM];
__device__ float g_K[MROWS * CDIM];
__device__ float g_V[MROWS * CDIM];
__device__ float g_Y[MROWS * CDIM];

// ---------------------------------------------------------------------------
// Tiled SGEMM body: C[M,Nn] = A[M,K] @ Bm[K,Nn] + bias, 128x128 tile, BK=8,
// 256 threads, 8x8 per-thread microtile.
// ---------------------------------------------------------------------------
__device__ __forceinline__ void sgemm_body(
    const float* __restrict__ A,
    const float* __restrict__ Bm,
    const float* __restrict__ bias,
    float* __restrict__ Cout,
    int K, int Nn, int bm, int bn)
{
    __shared__ float As[8][128];
    __shared__ float Bs[8][128];

    const int tid = threadIdx.x;
    const int tx  = tid & 15;        // 0..15
    const int ty  = tid >> 4;        // 0..15
    const int row0 = bm * 128;
    const int col0 = bn * 128;

    const int arow = tid >> 1;       // 0..127
    const int acol = (tid & 1) * 4;  // 0 or 4
    const int brow = tid >> 5;       // 0..7
    const int bcol = (tid & 31) * 4; // 0..124

    float acc[8][8];
#pragma unroll
    for (int i = 0; i < 8; i++)
#pragma unroll
        for (int j = 0; j < 8; j++) acc[i][j] = 0.0f;

    for (int k0 = 0; k0 < K; k0 += 8) {
        // Load A tile (transposed into As[k][m]) and B tile
        float4 av = *(const float4*)&A[(size_t)(row0 + arow) * K + k0 + acol];
        As[acol + 0][arow] = av.x;
        As[acol + 1][arow] = av.y;
        As[acol + 2][arow] = av.z;
        As[acol + 3][arow] = av.w;
        float4 bv = *(const float4*)&Bm[(size_t)(k0 + brow) * Nn + col0 + bcol];
        *(float4*)&Bs[brow][bcol] = bv;
        __syncthreads();

#pragma unroll
        for (int kk = 0; kk < 8; kk++) {
            float a[8], b[8];
            *(float4*)(a)     = *(const float4*)&As[kk][ty * 8];
            *(float4*)(a + 4) = *(const float4*)&As[kk][ty * 8 + 4];
            *(float4*)(b)     = *(const float4*)&Bs[kk][tx * 8];
            *(float4*)(b + 4) = *(const float4*)&Bs[kk][tx * 8 + 4];
#pragma unroll
            for (int i = 0; i < 8; i++)
#pragma unroll
                for (int j = 0; j < 8; j++)
                    acc[i][j] += a[i] * b[j];
        }
        __syncthreads();
    }

    // Epilogue: add bias, store
#pragma unroll
    for (int i = 0; i < 8; i++) {
        int r = row0 + ty * 8 + i;
#pragma unroll
        for (int j = 0; j < 8; j += 4) {
            int c = col0 + tx * 8 + j;
            float4 o;
            o.x = acc[i][j + 0] + bias[c + 0];
            o.y = acc[i][j + 1] + bias[c + 1];
            o.z = acc[i][j + 2] + bias[c + 2];
            o.w = acc[i][j + 3] + bias[c + 3];
            *(float4*)&Cout[(size_t)r * Nn + c] = o;
        }
    }
}

// Fused QKV projection: blockIdx.z selects projection (0=Q,1=K,2=V)
__global__ void __launch_bounds__(256)
qkv_gemm_kernel(const float* __restrict__ x,
                const float* __restrict__ Wq, const float* __restrict__ bq,
                const float* __restrict__ Wk, const float* __restrict__ bk,
                const float* __restrict__ Wv, const float* __restrict__ bv)
{
    int p = blockIdx.z;
    const float* W = (p == 0) ? Wq : (p == 1) ? Wk : Wv;
    const float* b = (p == 0) ? bq : (p == 1) ? bk : bv;
    float* out     = (p == 0) ? g_Q : (p == 1) ? g_K : g_V;
    sgemm_body(x, W, b, out, CDIM, CDIM, blockIdx.y, blockIdx.x);
}

// Output projection: out = Y @ Wp + bp
__global__ void __launch_bounds__(256)
proj_gemm_kernel(const float* __restrict__ Wp, const float* __restrict__ bp,
                 float* __restrict__ out)
{
    sgemm_body(g_Y, Wp, bp, out, CDIM, CDIM, blockIdx.y, blockIdx.x);
}

// ---------------------------------------------------------------------------
// Flash attention: grid (NSEQ/128, HH, BSZ), 128 threads; 1 thread = 1 q row.
// q[64] and o[64] live in registers; K/V streamed through smem in 64-row
// tiles; online softmax with lazy max-rescale.
// ---------------------------------------------------------------------------
__global__ void __launch_bounds__(128)
attn_kernel()
{
    const int qt = blockIdx.x;
    const int h  = blockIdx.y;
    const int b  = blockIdx.z;
    const int t  = threadIdx.x;
    const int n  = qt * 128 + t;

    __shared__ float ks[64][64];
    __shared__ float vs[64][64];

    // Load this thread's query row, pre-scaled by 1/sqrt(DH)
    const float scale = 0.125f;
    float q[64];
    const float* qptr = &g_Q[((size_t)(b * NSEQ + n)) * CDIM + h * DHD];
#pragma unroll
    for (int d = 0; d < 64; d += 4) {
        float4 qv = *(const float4*)&qptr[d];
        q[d + 0] = qv.x * scale;
        q[d + 1] = qv.y * scale;
        q[d + 2] = qv.z * scale;
        q[d + 3] = qv.w * scale;
    }

    float o[64];
#pragma unroll
    for (int d = 0; d < 64; d++) o[d] = 0.0f;
    float m = -1e30f, l = 0.0f;

    for (int jt = 0; jt < NSEQ; jt += 64) {
        __syncthreads();
        // Cooperative K/V tile load: 64 rows x 64 floats each
#pragma unroll
        for (int i = 0; i < 8; i++) {
            int idx = t + i * 128;        // float4 index 0..1023
            int r   = idx >> 4;
            int d4  = (idx & 15) << 2;
            size_t base = ((size_t)(b * NSEQ + jt + r)) * CDIM + h * DHD + d4;
            *(float4*)&ks[r][d4] = *(const float4*)&g_K[base];
            *(float4*)&vs[r][d4] = *(const float4*)&g_V[base];
        }
        __syncthreads();

#pragma unroll 2
        for (int j = 0; j < 64; j++) {
            float s = 0.0f;
#pragma unroll
            for (int d = 0; d < 64; d += 4) {
                float4 kv = *(const float4*)&ks[j][d];
                s += q[d + 0] * kv.x + q[d + 1] * kv.y
                   + q[d + 2] * kv.z + q[d + 3] * kv.w;
            }
            if (s > m) {   // rare rescale path (~ln(N) per row)
                float corr = __expf(m - s);
                l *= corr;
#pragma unroll
                for (int d = 0; d < 64; d++) o[d] *= corr;
                m = s;
            }
            float p = __expf(s - m);
            l += p;
#pragma unroll
            for (int d = 0; d < 64; d += 4) {
                float4 vv = *(const float4*)&vs[j][d];
                o[d + 0] += p * vv.x;
                o[d + 1] += p * vv.y;
                o[d + 2] += p * vv.z;
                o[d + 3] += p * vv.w;
            }
        }
    }

    const float inv = 1.0f / l;
    float* yp = &g_Y[((size_t)(b * NSEQ + n)) * CDIM + h * DHD];
#pragma unroll
    for (int d = 0; d < 64; d += 4) {
        float4 ov;
        ov.x = o[d + 0] * inv;
        ov.y = o[d + 1] * inv;
        ov.z = o[d + 2] * inv;
        ov.w = o[d + 3] * inv;
        *(float4*)&yp[d] = ov;
    }
}

// ---------------------------------------------------------------------------
extern "C" void kernel_launch(void* const* d_in, const int* in_sizes, int n_in,
                              void* d_out, int out_size)
{
    const float* x  = (const float*)d_in[0];
    const float* Wq = (const float*)d_in[1];
    const float* bq = (const float*)d_in[2];
    const float* Wk = (const float*)d_in[3];
    const float* bk = (const float*)d_in[4];
    const float* Wv = (const float*)d_in[5];
    const float* bv = (const float*)d_in[6];
    const float* Wp = (const float*)d_in[7];
    const float* bp = (const float*)d_in[8];
    float* out = (float*)d_out;

    // QKV projections (fused grid: z = projection index)
    dim3 qkv_grid(CDIM / 128, MROWS / 128, 3);
    qkv_gemm_kernel<<<qkv_grid, 256>>>(x, Wq, bq, Wk, bk, Wv, bv);

    // Flash attention
    dim3 attn_grid(NSEQ / 128, HH, BSZ);
    attn_kernel<<<attn_grid, 128>>>();

    // Output projection
    dim3 proj_grid(CDIM / 128, MROWS / 128, 1);
    proj_gemm_kernel<<<proj_grid, 256>>>(Wp, bp, out);
}